// round 15
// baseline (speedup 1.0000x reference)
#include <cuda_runtime.h>
#include <cuda_fp16.h>
#include <cstdint>

// ---------------------------------------------------------------------------
// Problem constants
// ---------------------------------------------------------------------------
#define IN_DIM   4096
#define OUT_DIM  4096
#define BATCH    8192
#define HASH_A   10007
#define HASH_B   20011
#define HASH_C_L 120027      // HASH_C * LAYER_ID(3)
#define SGN_A    4099
#define SGN_B    6151
#define SGN_C_L  44661       // SIGN_HASH_C * 3

// GEMM tiling (fp16): K-stage 64 halves = 128B rows
#define TM 128
#define TN 128
#define TK 64
#define KTILES (IN_DIM / TK) // 64

#define A_TILE_BYTES (TM * 128)          // 16384
#define B_TILE_BYTES (TN * 128)          // 16384
#define STAGE_BYTES  (A_TILE_BYTES + B_TILE_BYTES)   // 32768
#define SMEM_TOTAL   (2 * STAGE_BYTES)               // 65536 -> 3 CTAs/SM

// Fused prep kernel grid split
#define W_BLOCKS ((OUT_DIM * IN_DIM / 8) / 256)              // 8192
#define X_BLOCKS (((size_t)BATCH * IN_DIM / 8) / 256)        // 16384

// ---------------------------------------------------------------------------
// Scratch: fp16 weight matrix [OUT_DIM, IN_DIM] K-major, fp16 copy of x
// ---------------------------------------------------------------------------
__device__ __half g_Wh[(size_t)OUT_DIM * IN_DIM];    // 32 MB
__device__ __half g_xh[(size_t)BATCH * IN_DIM];      // 64 MB

// ---------------------------------------------------------------------------
// PTX helpers (base-PTX only: cp.async, ldmatrix, mma.sync)
// ---------------------------------------------------------------------------
__device__ __forceinline__ uint32_t smem_u32(const void* p) {
    uint32_t a;
    asm("{ .reg .u64 t; cvta.to.shared.u64 t, %1; cvt.u32.u64 %0, t; }" : "=r"(a) : "l"(p));
    return a;
}

__device__ __forceinline__ void cp_async16(uint32_t saddr, const void* gptr) {
    asm volatile("cp.async.cg.shared.global [%0], [%1], 16;" :: "r"(saddr), "l"(gptr) : "memory");
}
#define CP_COMMIT() asm volatile("cp.async.commit_group;" ::: "memory")
#define CP_WAIT0()  asm volatile("cp.async.wait_group 0;" ::: "memory")

__device__ __forceinline__ void ldsm4(uint32_t* r, uint32_t addr) {
    asm volatile("ldmatrix.sync.aligned.m8n8.x4.shared.b16 {%0,%1,%2,%3}, [%4];"
        : "=r"(r[0]), "=r"(r[1]), "=r"(r[2]), "=r"(r[3]) : "r"(addr));
}

__device__ __forceinline__ void mma_f16(float* c, const uint32_t* a, uint32_t b0, uint32_t b1) {
    asm volatile(
        "mma.sync.aligned.m16n8k16.row.col.f32.f16.f16.f32 "
        "{%0,%1,%2,%3}, {%4,%5,%6,%7}, {%8,%9}, {%0,%1,%2,%3};"
        : "+f"(c[0]), "+f"(c[1]), "+f"(c[2]), "+f"(c[3])
        : "r"(a[0]), "r"(a[1]), "r"(a[2]), "r"(a[3]), "r"(b0), "r"(b1));
}

// ---------------------------------------------------------------------------
// Kernel 1 (fused prep):
//   blocks [0, W_BLOCKS)            : W[o][i] = fp16(codebook[hash] * sign)
//   blocks [W_BLOCKS, W_BLOCKS+X_B) : xh = fp16(x)
// ---------------------------------------------------------------------------
__global__ void __launch_bounds__(256) prep_kernel(const float* __restrict__ cb,
                                                   const float* __restrict__ x,
                                                   __half* __restrict__ W,
                                                   __half* __restrict__ xh) {
    int bid = blockIdx.x;
    if (bid < W_BLOCKS) {
        int t = bid * blockDim.x + threadIdx.x;
        int base = t << 3;
        int o = base >> 12;
        int i = base & (IN_DIM - 1);
        int h0 = o * HASH_A + HASH_C_L;
        int s0 = o * SGN_A + SGN_C_L;
        __half w[8];
#pragma unroll
        for (int j = 0; j < 8; j++) {
            int ij = i + j;
            int h = (h0 + ij * HASH_B) & 65535;
            int sgn = (s0 + ij * SGN_B) & 1;
            float v = __ldg(cb + h);
            v = sgn ? v : -v;                            // bit 1 -> +1, bit 0 -> -1
            w[j] = __float2half_rn(v);
        }
        *reinterpret_cast<uint4*>(W + base) = *reinterpret_cast<uint4*>(w);
    } else {
        size_t t = (size_t)(bid - W_BLOCKS) * blockDim.x + threadIdx.x;
        size_t base = t << 3;
        float4 a = reinterpret_cast<const float4*>(x + base)[0];
        float4 b = reinterpret_cast<const float4*>(x + base)[1];
        __half2 h[4];
        h[0] = __floats2half2_rn(a.x, a.y);
        h[1] = __floats2half2_rn(a.z, a.w);
        h[2] = __floats2half2_rn(b.x, b.y);
        h[3] = __floats2half2_rn(b.z, b.w);
        *reinterpret_cast<uint4*>(xh + base) = *reinterpret_cast<uint4*>(h);
    }
}

// ---------------------------------------------------------------------------
// Mainloop building blocks (forceinline; expanded twice in the 2x-unrolled loop)
// ---------------------------------------------------------------------------
__device__ __forceinline__ void issue_stage(uint32_t cpA, uint32_t cpB, uint32_t slot,
                                            const char* ga, const char* gb) {
#pragma unroll
    for (int s = 0; s < 8; s++) {
        cp_async16(cpA + slot + s * 2048, ga + (size_t)s * 16 * IN_DIM * 2);
        cp_async16(cpB + slot + s * 2048, gb + (size_t)s * 16 * IN_DIM * 2);
    }
    CP_COMMIT();
}

__device__ __forceinline__ void compute_stage(uint32_t aS, uint32_t bS,
                                              const uint32_t* co, float c[4][8][4]) {
#pragma unroll
    for (int ks = 0; ks < 4; ks++) {
        uint32_t a[4][4];
        uint32_t b[4][4];
#pragma unroll
        for (int mb = 0; mb < 4; mb++) ldsm4(a[mb], aS + mb * 2048 + co[ks]);
#pragma unroll
        for (int p = 0; p < 4; p++)    ldsm4(b[p], bS + p * 2048 + co[ks]);
#pragma unroll
        for (int mb = 0; mb < 4; mb++)
#pragma unroll
            for (int j = 0; j < 8; j++) {
                int p = j >> 1, o = j & 1;
                mma_f16(c[mb][j], a[mb], b[p][o], b[p][o + 2]);
            }
    }
}

// ---------------------------------------------------------------------------
// Kernel 2: pipelined fp16 mma.sync GEMM (round-12 structure, mainloop
//   manually unrolled x2 with explicit slot 0/1 bodies — no slot arithmetic
//   in the steady state).
//   CTA 128x128, 4 warps in 2x2, warp tile 64x64, K-stage 64 halves,
//   2-slot cp.async ring (depth-1), 3 CTAs/SM.
// ---------------------------------------------------------------------------
__global__ void __launch_bounds__(128, 3) gemm_kernel(
    const __half* __restrict__ x, const __half* __restrict__ W,
    const float* __restrict__ bias, float* __restrict__ out) {
    extern __shared__ char smem[];
    uint32_t sb = smem_u32(smem);

    int tid  = threadIdx.x;
    int lane = tid & 31;
    int wid  = tid >> 5;
    int wm   = wid >> 1;           // warp row (0..1)
    int wn   = wid & 1;            // warp col (0..1)

    // tile coords: n-inner rasterization (B stays L2-resident)
    int n0 = (blockIdx.x & 31) * TN;
    int m0 = (blockIdx.x >> 5) * TM;

    // ---- cp.async per-thread mapping --------------------------------------
    int cp_r     = tid >> 3;                 // base row (step adds 16)
    int cp_c     = tid & 7;                  // chunk
    int cp_csw   = cp_c ^ (cp_r & 7);        // swizzled chunk
    uint32_t cpA = sb + cp_r * 128 + cp_csw * 16;
    uint32_t cpB = cpA + A_TILE_BYTES;
    const char* gA = (const char*)(x + (size_t)(m0 + cp_r) * IN_DIM + cp_c * 8);
    const char* gB = (const char*)(W + (size_t)(n0 + cp_r) * IN_DIM + cp_c * 8);

    // ---- ldmatrix per-thread addresses ------------------------------------
    int hi  = lane >> 4;
    int swz = lane & 7;
    uint32_t aBase = sb + (wm * 64 + (lane & 15)) * 128;
    uint32_t bBase = sb + A_TILE_BYTES + (wn * 64 + (lane & 15)) * 128;
    uint32_t co[4];
#pragma unroll
    for (int ks = 0; ks < 4; ks++) co[ks] = (uint32_t)(((2 * ks + hi) ^ swz) << 4);

    float c[4][8][4];
#pragma unroll
    for (int mb = 0; mb < 4; mb++)
#pragma unroll
        for (int j = 0; j < 8; j++)
#pragma unroll
            for (int q = 0; q < 4; q++) c[mb][j][q] = 0.0f;

    // ---- prologue: stage 0 into slot 0 ------------------------------------
    issue_stage(cpA, cpB, 0, gA, gB);

    // ---- main loop, manually unrolled x2 (KTILES = 64 even) ---------------
    // step kt (even, slot 0): wait; sync; issue kt+1 -> slot 1; compute slot 0
    // step kt+1 (odd, slot 1): wait; sync; issue kt+2 -> slot 0; compute slot 1
    for (int kt = 0; kt < KTILES; kt += 2) {
        // ---- even step: compute slot 0 ----
        CP_WAIT0();
        __syncthreads();
        {
            const char* ga = gA + (size_t)(kt + 1) * 128;
            const char* gb = gB + (size_t)(kt + 1) * 128;
            issue_stage(cpA, cpB, STAGE_BYTES, ga, gb);      // -> slot 1
        }
        compute_stage(aBase, bBase, co, c);                  // slot 0

        // ---- odd step: compute slot 1 ----
        CP_WAIT0();
        __syncthreads();
        if (kt + 2 < KTILES) {
            const char* ga = gA + (size_t)(kt + 2) * 128;
            const char* gb = gB + (size_t)(kt + 2) * 128;
            issue_stage(cpA, cpB, 0, ga, gb);                // -> slot 0
        }
        compute_stage(aBase + STAGE_BYTES, bBase + STAGE_BYTES, co, c);  // slot 1
    }

    // ---- epilogue ---------------------------------------------------------
    int row0 = m0 + wm * 64 + (lane >> 2);
    int col0 = n0 + wn * 64 + 2 * (lane & 3);
    float2 bv[8];
#pragma unroll
    for (int j = 0; j < 8; j++) {
        bv[j].x = __ldg(bias + col0 + j * 8);
        bv[j].y = __ldg(bias + col0 + j * 8 + 1);
    }
#pragma unroll
    for (int mb = 0; mb < 4; mb++) {
        float* r0p = out + (size_t)(row0 + mb * 16) * OUT_DIM;
        float* r1p = r0p + 8 * OUT_DIM;
#pragma unroll
        for (int j = 0; j < 8; j++) {
            float2 v0 = { c[mb][j][0] + bv[j].x, c[mb][j][1] + bv[j].y };
            float2 v1 = { c[mb][j][2] + bv[j].x, c[mb][j][3] + bv[j].y };
            *reinterpret_cast<float2*>(r0p + col0 + j * 8) = v0;
            *reinterpret_cast<float2*>(r1p + col0 + j * 8) = v1;
        }
    }
}

// ---------------------------------------------------------------------------
// Host launch
// ---------------------------------------------------------------------------
extern "C" void kernel_launch(void* const* d_in, const int* in_sizes, int n_in,
                              void* d_out, int out_size) {
    const float* x        = (const float*)d_in[0];
    const float* codebook = (const float*)d_in[1];
    const float* bias     = (const float*)d_in[2];
    float* out            = (float*)d_out;

    void* wptr = nullptr;
    void* xptr = nullptr;
    cudaGetSymbolAddress(&wptr, g_Wh);
    cudaGetSymbolAddress(&xptr, g_xh);

    // 1) fused prep: materialize W (fp16) + convert x (fp16) in one launch
    prep_kernel<<<(unsigned)(W_BLOCKS + X_BLOCKS), 256>>>(
        codebook, x, (__half*)wptr, (__half*)xptr);

    // 2) GEMM
    static bool attr_set = false;
    if (!attr_set) {
        cudaFuncSetAttribute(gemm_kernel, cudaFuncAttributeMaxDynamicSharedMemorySize, SMEM_TOTAL);
        attr_set = true;
    }
    dim3 grid((BATCH / TM) * (OUT_DIM / TN));            // 64 * 32 = 2048 CTAs
    gemm_kernel<<<grid, 128, SMEM_TOTAL>>>((const __half*)xptr, (const __half*)wptr, bias, out);
}

// round 17
// speedup vs baseline: 1.9344x; 1.9344x over previous
#include <cuda_runtime.h>
#include <cuda_fp16.h>
#include <cstdint>

// ---------------------------------------------------------------------------
// Problem constants
// ---------------------------------------------------------------------------
#define IN_DIM   4096
#define OUT_DIM  4096
#define BATCH    8192
#define HASH_A   10007
#define HASH_B   20011
#define HASH_C_L 120027      // HASH_C * LAYER_ID(3)
// sign(o,i): all sign-hash constants odd => bit = (o+i+1)&1 => +1 iff (o+i) even

// GEMM tiling (fp16): K-stage 64 halves = 128B rows
#define TM 128
#define TN 128
#define TK 64
#define NSLOT 2              // double-buffered smem (64KB -> 3 CTAs/SM)
#define KTILES (IN_DIM / TK) // 64

#define A_TILE_BYTES (TM * 128)          // 16384
#define B_TILE_BYTES (TN * 128)          // 16384
#define STAGE_BYTES  (A_TILE_BYTES + B_TILE_BYTES)   // 32768
#define SMEM_TOTAL   (NSLOT * STAGE_BYTES)           // 65536

#define CB_SMEM_BYTES (65536 * 2)        // fp16 codebook in smem: 128 KB

// ---------------------------------------------------------------------------
// Scratch: fp16 weight matrix [OUT_DIM, IN_DIM] K-major, fp16 copy of x
// ---------------------------------------------------------------------------
__device__ __half g_Wh[(size_t)OUT_DIM * IN_DIM];    // 32 MB
__device__ __half g_xh[(size_t)BATCH * IN_DIM];      // 64 MB

// ---------------------------------------------------------------------------
// PTX helpers (base-PTX only: cp.async, ldmatrix, mma.sync)
// ---------------------------------------------------------------------------
__device__ __forceinline__ uint32_t smem_u32(const void* p) {
    uint32_t a;
    asm("{ .reg .u64 t; cvta.to.shared.u64 t, %1; cvt.u32.u64 %0, t; }" : "=r"(a) : "l"(p));
    return a;
}

__device__ __forceinline__ void cp_async16(uint32_t saddr, const void* gptr) {
    asm volatile("cp.async.cg.shared.global [%0], [%1], 16;" :: "r"(saddr), "l"(gptr) : "memory");
}
#define CP_COMMIT() asm volatile("cp.async.commit_group;" ::: "memory")
#define CP_WAIT0()  asm volatile("cp.async.wait_group 0;" ::: "memory")

__device__ __forceinline__ void ldsm4(uint32_t* r, uint32_t addr) {
    asm volatile("ldmatrix.sync.aligned.m8n8.x4.shared.b16 {%0,%1,%2,%3}, [%4];"
        : "=r"(r[0]), "=r"(r[1]), "=r"(r[2]), "=r"(r[3]) : "r"(addr));
}

__device__ __forceinline__ void mma_f16(float* c, const uint32_t* a, uint32_t b0, uint32_t b1) {
    asm volatile(
        "mma.sync.aligned.m16n8k16.row.col.f32.f16.f16.f32 "
        "{%0,%1,%2,%3}, {%4,%5,%6,%7}, {%8,%9}, {%0,%1,%2,%3};"
        : "+f"(c[0]), "+f"(c[1]), "+f"(c[2]), "+f"(c[3])
        : "r"(a[0]), "r"(a[1]), "r"(a[2]), "r"(a[3]), "r"(b0), "r"(b1));
}

// ---------------------------------------------------------------------------
// Kernel 1a: build W via smem-resident fp16 codebook (no random LDG).
//   grid 256 blocks x 256 threads; block handles 16 o-rows.
//   Each warp: 2 rows; lane L handles i = 64*it + 2L, 2L+1 (half2 stores).
//   LDS gather is conflict-free: lane-to-lane dh = 20011, bank step 11 (odd).
//   sign(o,i) = +1 iff (o+i) even; i even per lane slot 0 => sign depends
//   only on o parity, pair partner is the negation.
// ---------------------------------------------------------------------------
__global__ void __launch_bounds__(256) build_w_kernel(const float* __restrict__ cb,
                                                      __half* __restrict__ W) {
    extern __shared__ __half cbs[];      // 65536 fp16 entries (128 KB)
    int tid = threadIdx.x;

    // load + convert codebook into smem (coalesced float4 reads)
    const float4* cb4 = reinterpret_cast<const float4*>(cb);
#pragma unroll
    for (int it = 0; it < 64; it++) {
        int idx = it * 256 + tid;        // float4 index, 16384 total
        float4 v = cb4[idx];
        __half2 h01 = __floats2half2_rn(v.x, v.y);
        __half2 h23 = __floats2half2_rn(v.z, v.w);
        *reinterpret_cast<__half2*>(&cbs[idx * 4])     = h01;
        *reinterpret_cast<__half2*>(&cbs[idx * 4 + 2]) = h23;
    }
    __syncthreads();

    int lane = tid & 31;
    int wrp  = tid >> 5;                 // 0..7
    int o0   = blockIdx.x * 16;

#pragma unroll
    for (int r = 0; r < 2; r++) {
        int o = o0 + wrp * 2 + r;
        bool o_even = (o & 1) == 0;
        // h for i = 2*lane at it=0
        uint32_t h = (uint32_t)o * HASH_A + HASH_C_L + (uint32_t)(2 * lane) * HASH_B;
        __half2* wrow = reinterpret_cast<__half2*>(W + (size_t)o * IN_DIM) + lane;
#pragma unroll 4
        for (int it = 0; it < 64; it++) {
            __half a = cbs[h & 65535];
            __half b = cbs[(h + HASH_B) & 65535];
            __half2 pr = o_even ? __halves2half2(a, __hneg(b))
                                : __halves2half2(__hneg(a), b);
            wrow[it * 32] = pr;          // i = it*64 + 2*lane
            h += 64u * HASH_B;
        }
    }
}

// ---------------------------------------------------------------------------
// Kernel 1b: x fp32 -> fp16 (streaming, at BW floor)
// ---------------------------------------------------------------------------
__global__ void __launch_bounds__(256) convert_x_kernel(const float* __restrict__ x,
                                                        __half* __restrict__ xh) {
    size_t t = (size_t)blockIdx.x * blockDim.x + threadIdx.x;
    size_t base = t << 3;
    float4 a = reinterpret_cast<const float4*>(x + base)[0];
    float4 b = reinterpret_cast<const float4*>(x + base)[1];
    __half2 h[4];
    h[0] = __floats2half2_rn(a.x, a.y);
    h[1] = __floats2half2_rn(a.z, a.w);
    h[2] = __floats2half2_rn(b.x, b.y);
    h[3] = __floats2half2_rn(b.z, b.w);
    *reinterpret_cast<uint4*>(xh + base) = *reinterpret_cast<uint4*>(h);
}

// ---------------------------------------------------------------------------
// Kernel 2: pipelined fp16 mma.sync GEMM — EXACT round-12 source (662 us,
//   tensor 68.1%, regs 168 = 3-CTA ceiling). Do not restructure: every
//   rewrite (reg double-buffer, runtime trip counts, template dual loops,
//   manual unroll with param-passed accumulators) regressed via codegen.
//   CTA 128x128, 4 warps in 2x2, warp tile 64x64, K-stage 64 halves,
//   2-slot cp.async ring (depth-1), 3 CTAs/SM.
//   Layout: A[r][k], W[n][k] K-major, 128B rows, XOR-16B swizzle.
// ---------------------------------------------------------------------------
__global__ void __launch_bounds__(128, 3) gemm_kernel(
    const __half* __restrict__ x, const __half* __restrict__ W,
    const float* __restrict__ bias, float* __restrict__ out) {
    extern __shared__ char smem[];
    uint32_t sb = smem_u32(smem);

    int tid  = threadIdx.x;
    int lane = tid & 31;
    int wid  = tid >> 5;
    int wm   = wid >> 1;           // warp row (0..1)
    int wn   = wid & 1;            // warp col (0..1)

    // tile coords: n-inner rasterization (B stays L2-resident)
    int n0 = (blockIdx.x & 31) * TN;
    int m0 = (blockIdx.x >> 5) * TM;

    // ---- cp.async per-thread mapping --------------------------------------
    int cp_r     = tid >> 3;                 // base row (step adds 16)
    int cp_c     = tid & 7;                  // chunk
    int cp_csw   = cp_c ^ (cp_r & 7);        // swizzled chunk
    uint32_t cpA = sb + cp_r * 128 + cp_csw * 16;
    uint32_t cpB = cpA + A_TILE_BYTES;
    const char* gA = (const char*)(x + (size_t)(m0 + cp_r) * IN_DIM + cp_c * 8);
    const char* gB = (const char*)(W + (size_t)(n0 + cp_r) * IN_DIM + cp_c * 8);

    // ---- ldmatrix per-thread addresses ------------------------------------
    int hi  = lane >> 4;
    int swz = lane & 7;
    uint32_t aBase = sb + (wm * 64 + (lane & 15)) * 128;
    uint32_t bBase = sb + A_TILE_BYTES + (wn * 64 + (lane & 15)) * 128;
    uint32_t co[4];
#pragma unroll
    for (int ks = 0; ks < 4; ks++) co[ks] = (uint32_t)(((2 * ks + hi) ^ swz) << 4);

    float c[4][8][4];
#pragma unroll
    for (int mb = 0; mb < 4; mb++)
#pragma unroll
        for (int j = 0; j < 8; j++)
#pragma unroll
            for (int q = 0; q < 4; q++) c[mb][j][q] = 0.0f;

    // ---- prologue: stage 0 -------------------------------------------------
    {
#pragma unroll
        for (int s = 0; s < 8; s++) {
            cp_async16(cpA + s * 2048, gA + (size_t)s * 16 * IN_DIM * 2);
            cp_async16(cpB + s * 2048, gB + (size_t)s * 16 * IN_DIM * 2);
        }
        CP_COMMIT();
    }

    // ---- main loop: wait(kt) -> sync -> issue(kt+1) -> compute(kt) --------
    for (int kt = 0; kt < KTILES; kt++) {
        CP_WAIT0();
        __syncthreads();

        if (kt + 1 < KTILES) {
            int nk = kt + 1;
            uint32_t slot = (uint32_t)(nk & 1) * STAGE_BYTES;
            const char* ga = gA + (size_t)nk * 128;
            const char* gb = gB + (size_t)nk * 128;
#pragma unroll
            for (int s = 0; s < 8; s++) {
                cp_async16(cpA + slot + s * 2048, ga + (size_t)s * 16 * IN_DIM * 2);
                cp_async16(cpB + slot + s * 2048, gb + (size_t)s * 16 * IN_DIM * 2);
            }
            CP_COMMIT();
        }

        // compute on slot kt&1
        uint32_t slot = (uint32_t)(kt & 1) * STAGE_BYTES;
        uint32_t aS = aBase + slot;
        uint32_t bS = bBase + slot;
#pragma unroll
        for (int ks = 0; ks < 4; ks++) {
            uint32_t a[4][4];
            uint32_t b[4][4];
#pragma unroll
            for (int mb = 0; mb < 4; mb++) ldsm4(a[mb], aS + mb * 2048 + co[ks]);
#pragma unroll
            for (int p = 0; p < 4; p++)    ldsm4(b[p], bS + p * 2048 + co[ks]);
#pragma unroll
            for (int mb = 0; mb < 4; mb++)
#pragma unroll
                for (int j = 0; j < 8; j++) {
                    int p = j >> 1, o = j & 1;
                    mma_f16(c[mb][j], a[mb], b[p][o], b[p][o + 2]);
                }
        }
    }

    // ---- epilogue ---------------------------------------------------------
    int row0 = m0 + wm * 64 + (lane >> 2);
    int col0 = n0 + wn * 64 + 2 * (lane & 3);
    float2 bv[8];
#pragma unroll
    for (int j = 0; j < 8; j++) {
        bv[j].x = __ldg(bias + col0 + j * 8);
        bv[j].y = __ldg(bias + col0 + j * 8 + 1);
    }
#pragma unroll
    for (int mb = 0; mb < 4; mb++) {
        float* r0p = out + (size_t)(row0 + mb * 16) * OUT_DIM;
        float* r1p = r0p + 8 * OUT_DIM;
#pragma unroll
        for (int j = 0; j < 8; j++) {
            float2 v0 = { c[mb][j][0] + bv[j].x, c[mb][j][1] + bv[j].y };
            float2 v1 = { c[mb][j][2] + bv[j].x, c[mb][j][3] + bv[j].y };
            *reinterpret_cast<float2*>(r0p + col0 + j * 8) = v0;
            *reinterpret_cast<float2*>(r1p + col0 + j * 8) = v1;
        }
    }
}

// ---------------------------------------------------------------------------
// Host launch
// ---------------------------------------------------------------------------
extern "C" void kernel_launch(void* const* d_in, const int* in_sizes, int n_in,
                              void* d_out, int out_size) {
    const float* x        = (const float*)d_in[0];
    const float* codebook = (const float*)d_in[1];
    const float* bias     = (const float*)d_in[2];
    float* out            = (float*)d_out;

    void* wptr = nullptr;
    void* xptr = nullptr;
    cudaGetSymbolAddress(&wptr, g_Wh);
    cudaGetSymbolAddress(&xptr, g_xh);

    static bool attr_set = false;
    if (!attr_set) {
        cudaFuncSetAttribute(gemm_kernel, cudaFuncAttributeMaxDynamicSharedMemorySize, SMEM_TOTAL);
        cudaFuncSetAttribute(build_w_kernel, cudaFuncAttributeMaxDynamicSharedMemorySize, CB_SMEM_BYTES);
        attr_set = true;
    }

    // 1) prep: W via smem codebook gather; x fp32->fp16 streaming
    build_w_kernel<<<OUT_DIM / 16, 256, CB_SMEM_BYTES>>>(codebook, (__half*)wptr);
    convert_x_kernel<<<(unsigned)(((size_t)BATCH * IN_DIM / 8) / 256), 256>>>(x, (__half*)xptr);

    // 2) GEMM (frozen round-12 kernel)
    dim3 grid((BATCH / TM) * (OUT_DIM / TN));            // 64 * 32 = 2048 CTAs
    gemm_kernel<<<grid, 128, SMEM_TOTAL>>>((const __half*)xptr, (const __half*)wptr, bias, out);
}